// round 3
// baseline (speedup 1.0000x reference)
#include <cuda_runtime.h>

// ---------------- problem constants ----------------
#define NB 16          // batches
#define NC 2048        // nodes per batch
#define NL 256         // input feature len
#define NNODE 32768    // NB*NC
#define NEDGE 524288
#define EOUT 16
#define NH 4
#define ND 4
#define NG 4

// ---------------- device scratch ----------------
__device__ float g_x[NNODE * EOUT];       // embedded features (pre-SE-scale)
__device__ float g_s[NB * EOUT];          // SE gates
__device__ float g_feat[NNODE * EOUT];    // GAT features (N,H,D)
__device__ float g_el[NNODE * NH];
__device__ float g_er[NNODE * NH];
__device__ float g_denom[NNODE * NH];     // softmax denominators
__device__ float g_accum[NNODE * EOUT];   // unnormalized aggregate
__device__ float g_enc[NNODE * EOUT];     // encode (N,16)
__device__ float g_av[NNODE];             // hp @ wa
__device__ float g_cv[NNODE];             // hp @ wb

// vector atomic add (sm_90+)
__device__ __forceinline__ void red4(float* p, float a, float b, float c, float d) {
    asm volatile("red.global.add.v4.f32 [%0], {%1,%2,%3,%4};"
                 :: "l"(p), "f"(a), "f"(b), "f"(c), "f"(d) : "memory");
}

// packed fp32x2 helpers (Blackwell packed FP32 pipe, PTX ISA 8.6+, sm_100+)
__device__ __forceinline__ unsigned long long pack2(float lo, float hi) {
    unsigned long long r;
    asm("mov.b64 %0, {%1, %2};" : "=l"(r) : "f"(lo), "f"(hi));
    return r;
}
__device__ __forceinline__ void fma2(unsigned long long& d, unsigned long long a,
                                     unsigned long long b) {
    asm("fma.rn.f32x2 %0, %1, %2, %0;" : "+l"(d) : "l"(a), "l"(b));
}
__device__ __forceinline__ float2 unpack2(unsigned long long v) {
    float lo, hi;
    asm("mov.b64 {%0, %1}, %2;" : "=f"(lo), "=f"(hi) : "l"(v));
    return make_float2(lo, hi);
}

// ---------------- K1: x = feature @ emb_W^T + emb_b ----------------
// 256 threads/block, 1 row/thread, 128 blocks
__global__ void k1_emb(const float* __restrict__ feature,
                       const float* __restrict__ embW,
                       const float* __restrict__ embB) {
    __shared__ float sW[EOUT * NL];   // 16KB
    int t = threadIdx.x;
    {
        const float4* W4 = (const float4*)embW;
        float4* S4 = (float4*)sW;
        #pragma unroll
        for (int q = 0; q < 4; q++) S4[t + q * 256] = W4[t + q * 256];
    }
    __syncthreads();

    int r0 = blockIdx.x * 256 + t;
    const float4* f4 = (const float4*)feature + (size_t)r0 * 64;

    float acc0[EOUT];
    #pragma unroll
    for (int e = 0; e < EOUT; e++) acc0[e] = 0.0f;

    const float4* sW4 = (const float4*)sW;
    #pragma unroll 8
    for (int kv = 0; kv < 64; kv++) {
        float4 a = f4[kv];
        #pragma unroll
        for (int e = 0; e < EOUT; e++) {
            float4 wv = sW4[e * 64 + kv];
            acc0[e] += a.x * wv.x + a.y * wv.y + a.z * wv.z + a.w * wv.w;
        }
    }

    float bb[EOUT];
    #pragma unroll
    for (int e = 0; e < EOUT; e++) bb[e] = __ldg(&embB[e]);

    float4* X4 = (float4*)g_x;
    #pragma unroll
    for (int q = 0; q < 4; q++)
        X4[(size_t)r0 * 4 + q] = make_float4(acc0[q*4+0] + bb[q*4+0], acc0[q*4+1] + bb[q*4+1],
                                             acc0[q*4+2] + bb[q*4+2], acc0[q*4+3] + bb[q*4+3]);
}

// ---------------- K2: z = mean, s = SE gates. grid=16, block=512 ----------------
__global__ void k2_se(const float* __restrict__ seW1, const float* __restrict__ seb1,
                      const float* __restrict__ seW2, const float* __restrict__ seb2) {
    __shared__ float red[512];
    __shared__ float sres[EOUT];
    int b = blockIdx.x, t = threadIdx.x;
    int e = t & 15, slot = t >> 4;            // 32 slots x 16 e
    const float* xp = g_x + ((size_t)(b * NC + slot * 64) * EOUT) + e;
    float p = 0.0f;
    #pragma unroll 8
    for (int g = 0; g < 64; g++) p += xp[g * EOUT];
    red[t] = p;
    __syncthreads();
    if (t < 16) {
        float z = 0.0f;
        #pragma unroll
        for (int s2 = 0; s2 < 32; s2++) z += red[s2 * 16 + t];
        red[t] = z * (1.0f / 2048.0f);
    }
    __syncthreads();
    if (t == 0) {
        float t1[4];
        #pragma unroll
        for (int j = 0; j < 4; j++) {
            float v = seb1[j];
            #pragma unroll
            for (int e2 = 0; e2 < 16; e2++) v += red[e2] * seW1[j * 16 + e2];
            t1[j] = fmaxf(v, 0.0f);
        }
        #pragma unroll
        for (int e2 = 0; e2 < 16; e2++) {
            float v = seb2[e2];
            #pragma unroll
            for (int j = 0; j < 4; j++) v += t1[j] * seW2[e2 * 4 + j];
            sres[e2] = 1.0f / (1.0f + expf(-v));
        }
    }
    __syncthreads();
    if (t < 16) g_s[b * 16 + t] = sres[t];
}

// ---------------- K3: feat = (x*s) @ gat_W^T ; el ; er ; zero accumulators ----------------
__global__ void k3_feat(const float* __restrict__ gatW,
                        const float* __restrict__ attnL,
                        const float* __restrict__ attnR) {
    __shared__ float sGW[256], sAL[16], sAR[16];
    int t = threadIdx.x;
    sGW[t] = gatW[t];
    if (t < 16) { sAL[t] = attnL[t]; sAR[t] = attnR[t]; }
    __syncthreads();
    int n = blockIdx.x * 256 + t;
    int b = n >> 11;

    // zero the atomic accumulators for this node (replaces a separate kernel)
    float4 z4 = make_float4(0.0f, 0.0f, 0.0f, 0.0f);
    ((float4*)g_denom)[n] = z4;
    float4* AC4 = (float4*)g_accum + (size_t)n * 4;
    #pragma unroll
    for (int q = 0; q < 4; q++) AC4[q] = z4;

    float xs[16];
    const float4* X4 = (const float4*)g_x + (size_t)n * 4;
    const float4* S4 = (const float4*)g_s + b * 4;
    #pragma unroll
    for (int q = 0; q < 4; q++) {
        float4 xv = X4[q], sv = S4[q];
        xs[q*4+0] = xv.x * sv.x; xs[q*4+1] = xv.y * sv.y;
        xs[q*4+2] = xv.z * sv.z; xs[q*4+3] = xv.w * sv.w;
    }
    float feat[16];
    #pragma unroll
    for (int o = 0; o < 16; o++) {
        float f = 0.0f;
        #pragma unroll
        for (int e = 0; e < 16; e++) f += xs[e] * sGW[o * 16 + e];
        feat[o] = f;
    }
    float el[4], er[4];
    #pragma unroll
    for (int h = 0; h < 4; h++) {
        float a = 0.0f, c = 0.0f;
        #pragma unroll
        for (int d = 0; d < 4; d++) {
            a += feat[h*4+d] * sAL[h*4+d];
            c += feat[h*4+d] * sAR[h*4+d];
        }
        el[h] = a; er[h] = c;
    }
    float4* F4 = (float4*)g_feat;
    #pragma unroll
    for (int q = 0; q < 4; q++)
        F4[(size_t)n*4+q] = make_float4(feat[q*4], feat[q*4+1], feat[q*4+2], feat[q*4+3]);
    ((float4*)g_el)[n] = make_float4(el[0], el[1], el[2], el[3]);
    ((float4*)g_er)[n] = make_float4(er[0], er[1], er[2], er[3]);
}

// ---------------- KE: edge pass — exp + atomic aggregate ----------------
__global__ void ke_edge(const int* __restrict__ src, const int* __restrict__ dst) {
    int i = blockIdx.x * 256 + threadIdx.x;   // grid = 2048, covers NEDGE exactly
    int s = src[i], d = dst[i];
    float4 el = ((const float4*)g_el)[s];
    float4 er = ((const float4*)g_er)[d];
    const float4* F4 = (const float4*)g_feat;
    float4 f0 = F4[(size_t)s*4+0];
    float4 f1 = F4[(size_t)s*4+1];
    float4 f2 = F4[(size_t)s*4+2];
    float4 f3 = F4[(size_t)s*4+3];
    float e0 = el.x + er.x; e0 = e0 > 0.0f ? e0 : 0.2f * e0;
    float e1 = el.y + er.y; e1 = e1 > 0.0f ? e1 : 0.2f * e1;
    float e2 = el.z + er.z; e2 = e2 > 0.0f ? e2 : 0.2f * e2;
    float e3 = el.w + er.w; e3 = e3 > 0.0f ? e3 : 0.2f * e3;
    // softmax is shift-invariant; |e| small -> skip segment_max
    float w0 = __expf(e0), w1 = __expf(e1), w2 = __expf(e2), w3 = __expf(e3);
    // compute all products first, then issue the REDs back-to-back
    float p00=w0*f0.x, p01=w0*f0.y, p02=w0*f0.z, p03=w0*f0.w;
    float p10=w1*f1.x, p11=w1*f1.y, p12=w1*f1.z, p13=w1*f1.w;
    float p20=w2*f2.x, p21=w2*f2.y, p22=w2*f2.z, p23=w2*f2.w;
    float p30=w3*f3.x, p31=w3*f3.y, p32=w3*f3.z, p33=w3*f3.w;
    red4(&g_denom[(size_t)d * 4], w0, w1, w2, w3);
    red4(&g_accum[(size_t)d*16+ 0], p00, p01, p02, p03);
    red4(&g_accum[(size_t)d*16+ 4], p10, p11, p12, p13);
    red4(&g_accum[(size_t)d*16+ 8], p20, p21, p22, p23);
    red4(&g_accum[(size_t)d*16+12], p30, p31, p32, p33);
}

// ---------------- KF: normalize -> encode, hp, a/c ----------------
__global__ void kf_norm(const float* __restrict__ gatb,
                        const float* __restrict__ projW,
                        const float* __restrict__ projb,
                        const float* __restrict__ graphW) {
    int n = blockIdx.x * 256 + threadIdx.x;
    float4 dn = ((const float4*)g_denom)[n];
    float inv[4];
    inv[0] = dn.x > 0.0f ? 1.0f/dn.x : 0.0f;
    inv[1] = dn.y > 0.0f ? 1.0f/dn.y : 0.0f;
    inv[2] = dn.z > 0.0f ? 1.0f/dn.z : 0.0f;
    inv[3] = dn.w > 0.0f ? 1.0f/dn.w : 0.0f;
    float enc[16];
    const float4* A4 = (const float4*)g_accum + (size_t)n * 4;
    #pragma unroll
    for (int h = 0; h < 4; h++) {
        float4 v = A4[h];
        enc[h*4+0] = v.x * inv[h] + __ldg(&gatb[h*4+0]);
        enc[h*4+1] = v.y * inv[h] + __ldg(&gatb[h*4+1]);
        enc[h*4+2] = v.z * inv[h] + __ldg(&gatb[h*4+2]);
        enc[h*4+3] = v.w * inv[h] + __ldg(&gatb[h*4+3]);
    }
    float4* E4 = (float4*)g_enc;
    #pragma unroll
    for (int q = 0; q < 4; q++)
        E4[(size_t)n*4+q] = make_float4(enc[q*4], enc[q*4+1], enc[q*4+2], enc[q*4+3]);
    float a = 0.0f, c = 0.0f;
    #pragma unroll
    for (int g = 0; g < NG; g++) {
        float hp = __ldg(&projb[g]);
        #pragma unroll
        for (int o = 0; o < 16; o++) hp += enc[o] * __ldg(&projW[g*16+o]);
        a += hp * __ldg(&graphW[g]);
        c += hp * __ldg(&graphW[NG + g]);
    }
    g_av[n] = a;
    g_cv[n] = c;
}

// ---------------- KG: out[b,i,j] = w*dot(enc_i,enc_j) + (1-w)*(a_i+c_j) ----------------
// grid (16 jt, 16 it, 16 b), block 256 = 16x16 threads, 8x8 outputs each.
// Inner product uses packed fp32x2 FMA; w-tile loads issued before the FMA loop
// so their DRAM latency overlaps compute.
__global__ __launch_bounds__(256) void kg_graph(const float* __restrict__ w,
                                                float* __restrict__ out) {
    __shared__ __align__(16) float sI[16 * 128];   // [k][i]
    __shared__ __align__(16) float sJ[16 * 128];   // [k][j]
    int t = threadIdx.x;
    int b = blockIdx.z;
    int i0 = blockIdx.y * 128, j0 = blockIdx.x * 128;
    int nb = b * NC;

    const float4* ENC4 = (const float4*)g_enc;
    #pragma unroll
    for (int it = 0; it < 2; it++) {
        int q = t + it * 256;        // 512 float4 per tile side
        int row = q >> 2, c = q & 3;
        float4 v = ENC4[(size_t)(nb + i0 + row) * 4 + c];
        sI[(c*4+0)*128 + row] = v.x; sI[(c*4+1)*128 + row] = v.y;
        sI[(c*4+2)*128 + row] = v.z; sI[(c*4+3)*128 + row] = v.w;
        float4 u = ENC4[(size_t)(nb + j0 + row) * 4 + c];
        sJ[(c*4+0)*128 + row] = u.x; sJ[(c*4+1)*128 + row] = u.y;
        sJ[(c*4+2)*128 + row] = u.z; sJ[(c*4+3)*128 + row] = u.w;
    }

    int tx = t & 15, ty = t >> 4;
    int ibase = i0 + ty*8, jbase = j0 + tx*8;

    // issue w / av / cv loads early (DRAM latency overlaps the FMA loop)
    float4 Wt[8][2];
    #pragma unroll
    for (int ii = 0; ii < 8; ii++) {
        const float4* wr = (const float4*)(w + (size_t)(ibase + ii) * NC + jbase);
        Wt[ii][0] = wr[0]; Wt[ii][1] = wr[1];
    }
    const float4* Ap = (const float4*)(g_av + nb + ibase);
    const float4* Cp = (const float4*)(g_cv + nb + jbase);
    float4 a0 = Ap[0], a1 = Ap[1], c0 = Cp[0], c1 = Cp[1];

    __syncthreads();

    unsigned long long acc2[8][4];   // [ii][jj-pair]
    #pragma unroll
    for (int ii = 0; ii < 8; ii++)
        #pragma unroll
        for (int p = 0; p < 4; p++) acc2[ii][p] = 0ull;

    #pragma unroll
    for (int k = 0; k < 16; k++) {
        const float* pi = &sI[k*128 + ty*8];
        const float* pj = &sJ[k*128 + tx*8];
        float4 A0 = *(const float4*)pi, A1 = *(const float4*)(pi + 4);
        ulonglong2 Bp0 = *(const ulonglong2*)pj;
        ulonglong2 Bp1 = *(const ulonglong2*)(pj + 4);
        unsigned long long bj[4] = {Bp0.x, Bp0.y, Bp1.x, Bp1.y};
        float ei[8] = {A0.x,A0.y,A0.z,A0.w,A1.x,A1.y,A1.z,A1.w};
        unsigned long long ai[8];
        #pragma unroll
        for (int ii = 0; ii < 8; ii++) ai[ii] = pack2(ei[ii], ei[ii]);
        #pragma unroll
        for (int ii = 0; ii < 8; ii++)
            #pragma unroll
            for (int p = 0; p < 4; p++)
                fma2(acc2[ii][p], ai[ii], bj[p]);
    }

    float av[8] = {a0.x,a0.y,a0.z,a0.w,a1.x,a1.y,a1.z,a1.w};
    float cv[8] = {c0.x,c0.y,c0.z,c0.w,c1.x,c1.y,c1.z,c1.w};

    #pragma unroll
    for (int ii = 0; ii < 8; ii++) {
        float wv[8] = {Wt[ii][0].x,Wt[ii][0].y,Wt[ii][0].z,Wt[ii][0].w,
                       Wt[ii][1].x,Wt[ii][1].y,Wt[ii][1].z,Wt[ii][1].w};
        float r[8];
        #pragma unroll
        for (int p = 0; p < 4; p++) {
            float2 ac = unpack2(acc2[ii][p]);
            float g2a = av[ii] + cv[p*2+0];
            float g2b = av[ii] + cv[p*2+1];
            r[p*2+0] = fmaf(wv[p*2+0], ac.x - g2a, g2a);
            r[p*2+1] = fmaf(wv[p*2+1], ac.y - g2b, g2b);
        }
        float4* op = (float4*)(out + ((size_t)(nb + ibase + ii)) * NC + jbase);
        op[0] = make_float4(r[0], r[1], r[2], r[3]);
        op[1] = make_float4(r[4], r[5], r[6], r[7]);
    }
}

// ---------------- launcher ----------------
extern "C" void kernel_launch(void* const* d_in, const int* in_sizes, int n_in,
                              void* d_out, int out_size) {
    const float* feature = (const float*)d_in[0];
    const int*   src     = (const int*)d_in[1];
    const int*   dst     = (const int*)d_in[2];
    const float* embW    = (const float*)d_in[3];
    const float* embB    = (const float*)d_in[4];
    const float* seW1    = (const float*)d_in[5];
    const float* seb1    = (const float*)d_in[6];
    const float* seW2    = (const float*)d_in[7];
    const float* seb2    = (const float*)d_in[8];
    const float* gatW    = (const float*)d_in[9];
    const float* attnL   = (const float*)d_in[10];
    const float* attnR   = (const float*)d_in[11];
    const float* gatb    = (const float*)d_in[12];
    const float* projW   = (const float*)d_in[13];
    const float* projb   = (const float*)d_in[14];
    const float* graphW  = (const float*)d_in[15];
    const float* wmat    = (const float*)d_in[16];
    float* out = (float*)d_out;

    k1_emb<<<128, 256>>>(feature, embW, embB);
    k2_se<<<16, 512>>>(seW1, seb1, seW2, seb2);
    k3_feat<<<128, 256>>>(gatW, attnL, attnR);
    ke_edge<<<2048, 256>>>(src, dst);
    kf_norm<<<128, 256>>>(gatb, projW, projb, graphW);
    kg_graph<<<dim3(16, 16, 16), 256>>>(wmat, out);
}

// round 4
// speedup vs baseline: 1.0538x; 1.0538x over previous
#include <cuda_runtime.h>

// ---------------- problem constants ----------------
#define NB 16          // batches
#define NC 2048        // nodes per batch
#define NL 256         // input feature len
#define NNODE 32768    // NB*NC
#define NEDGE 524288
#define EOUT 16
#define NH 4
#define ND 4
#define NG 4

// ---------------- device scratch ----------------
__device__ float g_x[NNODE * EOUT];       // embedded features (pre-SE-scale)
__device__ float g_s[NB * EOUT];          // SE gates
__device__ float g_feat[NNODE * EOUT];    // GAT features (N,H,D)
__device__ float g_el[NNODE * NH];
__device__ float g_er[NNODE * NH];
__device__ float g_denom[NNODE * NH];     // softmax denominators
__device__ float g_accum[NNODE * EOUT];   // unnormalized aggregate
__device__ float g_enc[NNODE * EOUT];     // encode (N,16)
__device__ float g_av[NNODE];             // hp @ wa
__device__ float g_cv[NNODE];             // hp @ wb

// vector atomic add (sm_90+)
__device__ __forceinline__ void red4(float* p, float a, float b, float c, float d) {
    asm volatile("red.global.add.v4.f32 [%0], {%1,%2,%3,%4};"
                 :: "l"(p), "f"(a), "f"(b), "f"(c), "f"(d) : "memory");
}

// fp32 -> tf32 (round-to-nearest-even on the 10-bit mantissa)
__device__ __forceinline__ unsigned cvt_tf32(float f) {
    unsigned r;
    asm("cvt.rna.tf32.f32 %0, %1;" : "=r"(r) : "f"(f));
    return r;
}

// m16n8k8 tf32 mma: C += A(16x8,row) * B(8x8,col)
__device__ __forceinline__ void mma_tf32(float c[4], const unsigned a[4], const unsigned b[2]) {
    asm volatile(
        "mma.sync.aligned.m16n8k8.row.col.f32.tf32.tf32.f32 "
        "{%0,%1,%2,%3}, {%4,%5,%6,%7}, {%8,%9}, {%0,%1,%2,%3};"
        : "+f"(c[0]), "+f"(c[1]), "+f"(c[2]), "+f"(c[3])
        : "r"(a[0]), "r"(a[1]), "r"(a[2]), "r"(a[3]), "r"(b[0]), "r"(b[1]));
}

// ---------------- K1: x = feature @ emb_W^T + emb_b ----------------
__global__ void k1_emb(const float* __restrict__ feature,
                       const float* __restrict__ embW,
                       const float* __restrict__ embB) {
    __shared__ float sW[EOUT * NL];   // 16KB
    int t = threadIdx.x;
    {
        const float4* W4 = (const float4*)embW;
        float4* S4 = (float4*)sW;
        #pragma unroll
        for (int q = 0; q < 4; q++) S4[t + q * 256] = W4[t + q * 256];
    }
    __syncthreads();

    int r0 = blockIdx.x * 256 + t;
    const float4* f4 = (const float4*)feature + (size_t)r0 * 64;

    float acc0[EOUT];
    #pragma unroll
    for (int e = 0; e < EOUT; e++) acc0[e] = 0.0f;

    const float4* sW4 = (const float4*)sW;
    #pragma unroll 8
    for (int kv = 0; kv < 64; kv++) {
        float4 a = f4[kv];
        #pragma unroll
        for (int e = 0; e < EOUT; e++) {
            float4 wv = sW4[e * 64 + kv];
            acc0[e] += a.x * wv.x + a.y * wv.y + a.z * wv.z + a.w * wv.w;
        }
    }

    float bb[EOUT];
    #pragma unroll
    for (int e = 0; e < EOUT; e++) bb[e] = __ldg(&embB[e]);

    float4* X4 = (float4*)g_x;
    #pragma unroll
    for (int q = 0; q < 4; q++)
        X4[(size_t)r0 * 4 + q] = make_float4(acc0[q*4+0] + bb[q*4+0], acc0[q*4+1] + bb[q*4+1],
                                             acc0[q*4+2] + bb[q*4+2], acc0[q*4+3] + bb[q*4+3]);
}

// ---------------- K2: z = mean, s = SE gates. grid=16, block=512 ----------------
__global__ void k2_se(const float* __restrict__ seW1, const float* __restrict__ seb1,
                      const float* __restrict__ seW2, const float* __restrict__ seb2) {
    __shared__ float red[512];
    __shared__ float sres[EOUT];
    int b = blockIdx.x, t = threadIdx.x;
    int e = t & 15, slot = t >> 4;            // 32 slots x 16 e
    const float* xp = g_x + ((size_t)(b * NC + slot * 64) * EOUT) + e;
    float p = 0.0f;
    #pragma unroll 8
    for (int g = 0; g < 64; g++) p += xp[g * EOUT];
    red[t] = p;
    __syncthreads();
    if (t < 16) {
        float z = 0.0f;
        #pragma unroll
        for (int s2 = 0; s2 < 32; s2++) z += red[s2 * 16 + t];
        red[t] = z * (1.0f / 2048.0f);
    }
    __syncthreads();
    if (t == 0) {
        float t1[4];
        #pragma unroll
        for (int j = 0; j < 4; j++) {
            float v = seb1[j];
            #pragma unroll
            for (int e2 = 0; e2 < 16; e2++) v += red[e2] * seW1[j * 16 + e2];
            t1[j] = fmaxf(v, 0.0f);
        }
        #pragma unroll
        for (int e2 = 0; e2 < 16; e2++) {
            float v = seb2[e2];
            #pragma unroll
            for (int j = 0; j < 4; j++) v += t1[j] * seW2[e2 * 4 + j];
            sres[e2] = 1.0f / (1.0f + expf(-v));
        }
    }
    __syncthreads();
    if (t < 16) g_s[b * 16 + t] = sres[t];
}

// ---------------- K3: feat = (x*s) @ gat_W^T ; el ; er ; zero accumulators ----------------
__global__ void k3_feat(const float* __restrict__ gatW,
                        const float* __restrict__ attnL,
                        const float* __restrict__ attnR) {
    __shared__ float sGW[256], sAL[16], sAR[16];
    int t = threadIdx.x;
    sGW[t] = gatW[t];
    if (t < 16) { sAL[t] = attnL[t]; sAR[t] = attnR[t]; }
    __syncthreads();
    int n = blockIdx.x * 256 + t;
    int b = n >> 11;

    // zero the atomic accumulators for this node
    float4 z4 = make_float4(0.0f, 0.0f, 0.0f, 0.0f);
    ((float4*)g_denom)[n] = z4;
    float4* AC4 = (float4*)g_accum + (size_t)n * 4;
    #pragma unroll
    for (int q = 0; q < 4; q++) AC4[q] = z4;

    float xs[16];
    const float4* X4 = (const float4*)g_x + (size_t)n * 4;
    const float4* S4 = (const float4*)g_s + b * 4;
    #pragma unroll
    for (int q = 0; q < 4; q++) {
        float4 xv = X4[q], sv = S4[q];
        xs[q*4+0] = xv.x * sv.x; xs[q*4+1] = xv.y * sv.y;
        xs[q*4+2] = xv.z * sv.z; xs[q*4+3] = xv.w * sv.w;
    }
    float feat[16];
    #pragma unroll
    for (int o = 0; o < 16; o++) {
        float f = 0.0f;
        #pragma unroll
        for (int e = 0; e < 16; e++) f += xs[e] * sGW[o * 16 + e];
        feat[o] = f;
    }
    float el[4], er[4];
    #pragma unroll
    for (int h = 0; h < 4; h++) {
        float a = 0.0f, c = 0.0f;
        #pragma unroll
        for (int d = 0; d < 4; d++) {
            a += feat[h*4+d] * sAL[h*4+d];
            c += feat[h*4+d] * sAR[h*4+d];
        }
        el[h] = a; er[h] = c;
    }
    float4* F4 = (float4*)g_feat;
    #pragma unroll
    for (int q = 0; q < 4; q++)
        F4[(size_t)n*4+q] = make_float4(feat[q*4], feat[q*4+1], feat[q*4+2], feat[q*4+3]);
    ((float4*)g_el)[n] = make_float4(el[0], el[1], el[2], el[3]);
    ((float4*)g_er)[n] = make_float4(er[0], er[1], er[2], er[3]);
}

// ---------------- KE: edge pass — exp + atomic aggregate ----------------
__global__ void ke_edge(const int* __restrict__ src, const int* __restrict__ dst) {
    int i = blockIdx.x * 256 + threadIdx.x;   // grid = 2048, covers NEDGE exactly
    int s = src[i], d = dst[i];
    float4 el = ((const float4*)g_el)[s];
    float4 er = ((const float4*)g_er)[d];
    const float4* F4 = (const float4*)g_feat;
    float4 f0 = F4[(size_t)s*4+0];
    float4 f1 = F4[(size_t)s*4+1];
    float4 f2 = F4[(size_t)s*4+2];
    float4 f3 = F4[(size_t)s*4+3];
    float e0 = el.x + er.x; e0 = e0 > 0.0f ? e0 : 0.2f * e0;
    float e1 = el.y + er.y; e1 = e1 > 0.0f ? e1 : 0.2f * e1;
    float e2 = el.z + er.z; e2 = e2 > 0.0f ? e2 : 0.2f * e2;
    float e3 = el.w + er.w; e3 = e3 > 0.0f ? e3 : 0.2f * e3;
    // softmax is shift-invariant; |e| small -> skip segment_max
    float w0 = __expf(e0), w1 = __expf(e1), w2 = __expf(e2), w3 = __expf(e3);
    float p00=w0*f0.x, p01=w0*f0.y, p02=w0*f0.z, p03=w0*f0.w;
    float p10=w1*f1.x, p11=w1*f1.y, p12=w1*f1.z, p13=w1*f1.w;
    float p20=w2*f2.x, p21=w2*f2.y, p22=w2*f2.z, p23=w2*f2.w;
    float p30=w3*f3.x, p31=w3*f3.y, p32=w3*f3.z, p33=w3*f3.w;
    red4(&g_denom[(size_t)d * 4], w0, w1, w2, w3);
    red4(&g_accum[(size_t)d*16+ 0], p00, p01, p02, p03);
    red4(&g_accum[(size_t)d*16+ 4], p10, p11, p12, p13);
    red4(&g_accum[(size_t)d*16+ 8], p20, p21, p22, p23);
    red4(&g_accum[(size_t)d*16+12], p30, p31, p32, p33);
}

// ---------------- KF: normalize -> encode, hp, a/c ----------------
__global__ void kf_norm(const float* __restrict__ gatb,
                        const float* __restrict__ projW,
                        const float* __restrict__ projb,
                        const float* __restrict__ graphW) {
    int n = blockIdx.x * 256 + threadIdx.x;
    float4 dn = ((const float4*)g_denom)[n];
    float inv[4];
    inv[0] = dn.x > 0.0f ? 1.0f/dn.x : 0.0f;
    inv[1] = dn.y > 0.0f ? 1.0f/dn.y : 0.0f;
    inv[2] = dn.z > 0.0f ? 1.0f/dn.z : 0.0f;
    inv[3] = dn.w > 0.0f ? 1.0f/dn.w : 0.0f;
    float enc[16];
    const float4* A4 = (const float4*)g_accum + (size_t)n * 4;
    #pragma unroll
    for (int h = 0; h < 4; h++) {
        float4 v = A4[h];
        enc[h*4+0] = v.x * inv[h] + __ldg(&gatb[h*4+0]);
        enc[h*4+1] = v.y * inv[h] + __ldg(&gatb[h*4+1]);
        enc[h*4+2] = v.z * inv[h] + __ldg(&gatb[h*4+2]);
        enc[h*4+3] = v.w * inv[h] + __ldg(&gatb[h*4+3]);
    }
    float4* E4 = (float4*)g_enc;
    #pragma unroll
    for (int q = 0; q < 4; q++)
        E4[(size_t)n*4+q] = make_float4(enc[q*4], enc[q*4+1], enc[q*4+2], enc[q*4+3]);
    float a = 0.0f, c = 0.0f;
    #pragma unroll
    for (int g = 0; g < NG; g++) {
        float hp = __ldg(&projb[g]);
        #pragma unroll
        for (int o = 0; o < 16; o++) hp += enc[o] * __ldg(&projW[g*16+o]);
        a += hp * __ldg(&graphW[g]);
        c += hp * __ldg(&graphW[NG + g]);
    }
    g_av[n] = a;
    g_cv[n] = c;
}

// ---------------- KG: out[b,i,j] = w*dot(enc_i,enc_j) + (1-w)*(a_i+c_j) ----------------
// tf32 tensor-core version. Block = 128(i) x 64(j) tile, 256 threads = 8 warps.
// Warp w computes rows [i0 + w*16, +16) x all 64 j columns via 8 n-tiles of
// m16n8k8 mma (2 k-steps each). A/B fragments loaded once from L2-resident g_enc.
__global__ __launch_bounds__(256) void kg_graph(const float* __restrict__ w,
                                                float* __restrict__ out) {
    int b = blockIdx.z;
    int i0 = blockIdx.y * 128, j0 = blockIdx.x * 64;
    int nb = b * NC;
    int warp = threadIdx.x >> 5, lane = threadIdx.x & 31;
    int ra = lane >> 2, ca = lane & 3;      // A-frag row/col within tile

    const float* E = g_enc + (size_t)nb * EOUT;

    // ---- A fragments (16 rows x 16 k), 2 k-steps ----
    const float* Ar0 = E + (size_t)(i0 + warp * 16 + ra) * EOUT;
    const float* Ar1 = Ar0 + 8 * EOUT;
    unsigned a[2][4];
    #pragma unroll
    for (int s = 0; s < 2; s++) {
        a[s][0] = cvt_tf32(Ar0[s*8 + ca]);
        a[s][1] = cvt_tf32(Ar1[s*8 + ca]);
        a[s][2] = cvt_tf32(Ar0[s*8 + ca + 4]);
        a[s][3] = cvt_tf32(Ar1[s*8 + ca + 4]);
    }

    // ---- B fragments: 8 n-tiles x 2 k-steps x 2 regs ----
    // b0 = B[k=ca,   n=ra] = E[j0 + t*8 + ra, s*8 + ca]
    // b1 = B[k=ca+4, n=ra]
    unsigned bf[8][2][2];
    const float* Bb = E + (size_t)(j0 + ra) * EOUT + ca;
    #pragma unroll
    for (int t2 = 0; t2 < 8; t2++) {
        const float* Bt = Bb + (size_t)t2 * 8 * EOUT;
        bf[t2][0][0] = cvt_tf32(Bt[0]);
        bf[t2][0][1] = cvt_tf32(Bt[4]);
        bf[t2][1][0] = cvt_tf32(Bt[8]);
        bf[t2][1][1] = cvt_tf32(Bt[12]);
    }

    // ---- MMA: 8 tiles x 2 k-steps ----
    float c[8][4];
    #pragma unroll
    for (int t2 = 0; t2 < 8; t2++) {
        c[t2][0] = c[t2][1] = c[t2][2] = c[t2][3] = 0.0f;
        mma_tf32(c[t2], a[0], bf[t2][0]);
        mma_tf32(c[t2], a[1], bf[t2][1]);
    }

    // ---- epilogue: blend with w and graph2 ----
    int irow0 = i0 + warp * 16 + ra;          // local i of c0/c1
    int irow1 = irow0 + 8;                    // local i of c2/c3
    float av0 = g_av[nb + irow0];
    float av1 = g_av[nb + irow1];

    const float* wr0 = w + (size_t)irow0 * NC;
    const float* wr1 = w + (size_t)irow1 * NC;
    float* or0 = out + (size_t)(nb + irow0) * NC;
    float* or1 = out + (size_t)(nb + irow1) * NC;

    #pragma unroll
    for (int t2 = 0; t2 < 8; t2++) {
        int jc = j0 + t2 * 8 + 2 * ca;        // local j of c0/c2 (c1/c3 = jc+1)
        float2 cvp = *(const float2*)(g_cv + nb + jc);
        float2 w0 = *(const float2*)(wr0 + jc);
        float2 w1 = *(const float2*)(wr1 + jc);
        float g00 = av0 + cvp.x, g01 = av0 + cvp.y;
        float g10 = av1 + cvp.x, g11 = av1 + cvp.y;
        float2 r0, r1;
        r0.x = fmaf(w0.x, c[t2][0] - g00, g00);
        r0.y = fmaf(w0.y, c[t2][1] - g01, g01);
        r1.x = fmaf(w1.x, c[t2][2] - g10, g10);
        r1.y = fmaf(w1.y, c[t2][3] - g11, g11);
        *(float2*)(or0 + jc) = r0;
        *(float2*)(or1 + jc) = r1;
    }
}

// ---------------- launcher ----------------
extern "C" void kernel_launch(void* const* d_in, const int* in_sizes, int n_in,
                              void* d_out, int out_size) {
    const float* feature = (const float*)d_in[0];
    const int*   src     = (const int*)d_in[1];
    const int*   dst     = (const int*)d_in[2];
    const float* embW    = (const float*)d_in[3];
    const float* embB    = (const float*)d_in[4];
    const float* seW1    = (const float*)d_in[5];
    const float* seb1    = (const float*)d_in[6];
    const float* seW2    = (const float*)d_in[7];
    const float* seb2    = (const float*)d_in[8];
    const float* gatW    = (const float*)d_in[9];
    const float* attnL   = (const float*)d_in[10];
    const float* attnR   = (const float*)d_in[11];
    const float* gatb    = (const float*)d_in[12];
    const float* projW   = (const float*)d_in[13];
    const float* projb   = (const float*)d_in[14];
    const float* graphW  = (const float*)d_in[15];
    const float* wmat    = (const float*)d_in[16];
    float* out = (float*)d_out;

    k1_emb<<<128, 256>>>(feature, embW, embB);
    k2_se<<<16, 512>>>(seW1, seb1, seW2, seb2);
    k3_feat<<<128, 256>>>(gatW, attnL, attnR);
    ke_edge<<<2048, 256>>>(src, dst);
    kf_norm<<<128, 256>>>(gatb, projW, projb, graphW);
    kg_graph<<<dim3(32, 16, 16), 256>>>(wmat, out);
}